// round 1
// baseline (speedup 1.0000x reference)
#include <cuda_runtime.h>
#include <cuda_fp16.h>
#include <cstdint>

#define D128 128
#define MAXNODES 50000
#define PADK 136   // halfs per smem row (128 + 8 pad)

// Scratch: per-node transformed features, fp16.
// Y[n, 0:128]  = x[n] @ W1a   (used when n is a src)
// Y[n,128:256] = x[n] @ W1b   (used when n is a dst)
__device__ __half g_Y[(size_t)MAXNODES * 256];
__device__ int g_idx64;

// ---------------------------------------------------------------------------
// Detect edge_index dtype (int64 vs int32) at runtime.
// int64 little-endian with values < 2^31  => every odd 32-bit word is 0.
// int32 random indices => odd words are nonzero with overwhelming probability.
// ---------------------------------------------------------------------------
__global__ void detect_idx_kernel(const unsigned int* __restrict__ words) {
    __shared__ int nz;
    if (threadIdx.x == 0) nz = 0;
    __syncthreads();
    for (int i = threadIdx.x; i < 1024; i += blockDim.x) {
        if (words[2 * i + 1] != 0u) atomicOr(&nz, 1);
    }
    __syncthreads();
    if (threadIdx.x == 0) g_idx64 = (nz == 0) ? 1 : 0;
}

// ---------------------------------------------------------------------------
// Warp-level 16x128x128 GEMM using mma.sync.m16n8k16.f16 (fp32 accum).
// Arow: smem ptr to this warp's 16-row strip, row stride PADK halfs.
// Bs:   smem [128][PADK], Bs[n*PADK + k] = B[k][n]  (transposed, n-major)
// acc:  [16 n-tiles][4 floats]
// ---------------------------------------------------------------------------
__device__ __forceinline__ void warp_mma_16x128(
    const __half* __restrict__ Arow, const __half* __restrict__ Bs,
    float acc[16][4], int lane)
{
    const int g = lane >> 2, t = lane & 3;
    #pragma unroll
    for (int k0 = 0; k0 < 128; k0 += 16) {
        unsigned a0 = *(const unsigned*)(Arow + (size_t)g      * PADK + k0 + 2 * t);
        unsigned a1 = *(const unsigned*)(Arow + (size_t)(g + 8)* PADK + k0 + 2 * t);
        unsigned a2 = *(const unsigned*)(Arow + (size_t)g      * PADK + k0 + 2 * t + 8);
        unsigned a3 = *(const unsigned*)(Arow + (size_t)(g + 8)* PADK + k0 + 2 * t + 8);
        #pragma unroll
        for (int n = 0; n < 16; n++) {
            const __half* brow = Bs + (size_t)(n * 8 + g) * PADK + k0 + 2 * t;
            unsigned b0 = *(const unsigned*)(brow);
            unsigned b1 = *(const unsigned*)(brow + 8);
            asm volatile(
                "mma.sync.aligned.m16n8k16.row.col.f32.f16.f16.f32 "
                "{%0,%1,%2,%3}, {%4,%5,%6,%7}, {%8,%9}, {%0,%1,%2,%3};\n"
                : "+f"(acc[n][0]), "+f"(acc[n][1]), "+f"(acc[n][2]), "+f"(acc[n][3])
                : "r"(a0), "r"(a1), "r"(a2), "r"(a3), "r"(b0), "r"(b1));
        }
    }
}

// ---------------------------------------------------------------------------
// Kernel 1: Y[:, half_sel*128 : +128] = x @ W1[half_sel*128 : +128, :]
// grid (ceil(N/128), 2), block 256 (8 warps). Each warp: 16 rows x 128 cols.
// ---------------------------------------------------------------------------
__global__ void node_gemm_kernel(const float* __restrict__ x,
                                 const float* __restrict__ W1,
                                 int n_nodes)
{
    extern __shared__ __half smem[];
    __half* As = smem;                      // [128][PADK]
    __half* Bs = smem + 128 * PADK;         // [128][PADK], Bs[n][k] = W1[k+off][n]

    const int row0 = blockIdx.x * 128;
    const int half_sel = blockIdx.y;
    const int tid = threadIdx.x;

    // Load x tile (fp32 -> fp16), vectorized float4, zero-pad OOB rows.
    for (int i = tid; i < 128 * 32; i += 256) {
        int r = i >> 5, c4 = i & 31;
        int gr = row0 + r;
        float4 v = make_float4(0.f, 0.f, 0.f, 0.f);
        if (gr < n_nodes) v = ((const float4*)x)[(size_t)gr * 32 + c4];
        __half* dst = As + (size_t)r * PADK + c4 * 4;
        dst[0] = __float2half(v.x); dst[1] = __float2half(v.y);
        dst[2] = __float2half(v.z); dst[3] = __float2half(v.w);
    }
    // Load W1 slab transposed: Bs[n][k] = W1[(k + 128*half_sel)*128 + n]
    for (int i = tid; i < 128 * 128; i += 256) {
        int k = i >> 7, n = i & 127;   // consecutive tid -> consecutive n (coalesced)
        Bs[(size_t)n * PADK + k] =
            __float2half(W1[(size_t)(k + 128 * half_sel) * 128 + n]);
    }
    __syncthreads();

    const int warp = tid >> 5, lane = tid & 31;
    float acc[16][4];
    #pragma unroll
    for (int n = 0; n < 16; n++)
        acc[n][0] = acc[n][1] = acc[n][2] = acc[n][3] = 0.f;

    warp_mma_16x128(As + (size_t)warp * 16 * PADK, Bs, acc, lane);

    const int g = lane >> 2, t = lane & 3;
    const int r0 = row0 + warp * 16 + g;
    __half* Yb = g_Y + (size_t)half_sel * 128;
    #pragma unroll
    for (int n = 0; n < 16; n++) {
        int col = n * 8 + 2 * t;
        if (r0 < n_nodes)
            *(__half2*)(Yb + (size_t)r0 * 256 + col) =
                __floats2half2_rn(acc[n][0], acc[n][1]);
        if (r0 + 8 < n_nodes)
            *(__half2*)(Yb + (size_t)(r0 + 8) * 256 + col) =
                __floats2half2_rn(acc[n][2], acc[n][3]);
    }
}

// ---------------------------------------------------------------------------
// Kernel 2: per tile of 128 edges:
//   h = relu(Y[src,:128] + Y[dst,128:] + b1);  out = h @ W2 + b2
// grid (ceil(E/128)), block 256 (8 warps).
// ---------------------------------------------------------------------------
__global__ void edge_kernel(const void* __restrict__ edge_index,
                            const float* __restrict__ b1,
                            const float* __restrict__ W2,
                            const float* __restrict__ b2,
                            float* __restrict__ out,
                            int n_edges)
{
    extern __shared__ __half smem[];
    __half* Hs = smem;                      // [128][PADK]  h tile
    __half* Ws = smem + 128 * PADK;         // Ws[n][k] = W2[k][n]

    const int tid = threadIdx.x;
    const int e0 = blockIdx.x * 128;

    // Load W2 transposed (fp32 -> fp16), coalesced on global side.
    for (int i = tid; i < 128 * 128; i += 256) {
        int k = i >> 7, n = i & 127;
        Ws[(size_t)n * PADK + k] = __float2half(W2[i]);  // W2[k*128+n] == W2[i]
    }

    // Gather + bias + relu: 2 threads per edge, 64 cols each.
    const int is64 = g_idx64;
    const long long* idx64 = (const long long*)edge_index;
    const int*       idx32 = (const int*)edge_index;

    const int er = tid >> 1;
    const int cbase = (tid & 1) * 64;
    const int e = e0 + er;

    if (e < n_edges) {
        long long s, d;
        if (is64) { s = idx64[e]; d = idx64[(size_t)n_edges + e]; }
        else      { s = idx32[e]; d = idx32[(size_t)n_edges + e]; }
        const __half* Ya = g_Y + (size_t)s * 256;          // src half
        const __half* Yd = g_Y + (size_t)d * 256 + 128;    // dst half
        #pragma unroll
        for (int j = 0; j < 64; j += 8) {
            int c = cbase + j;
            uint4 va = *(const uint4*)(Ya + c);
            uint4 vb = *(const uint4*)(Yd + c);
            const __half2* ha = (const __half2*)&va;
            const __half2* hb = (const __half2*)&vb;
            __half2 r[4];
            #pragma unroll
            for (int q = 0; q < 4; q++) {
                float2 fa = __half22float2(ha[q]);
                float2 fb = __half22float2(hb[q]);
                float2 bb = *(const float2*)(b1 + c + 2 * q);
                float vx = fmaxf(fa.x + fb.x + bb.x, 0.f);
                float vy = fmaxf(fa.y + fb.y + bb.y, 0.f);
                r[q] = __floats2half2_rn(vx, vy);
            }
            *(uint4*)(Hs + (size_t)er * PADK + c) = *(const uint4*)r;
        }
    } else {
        uint4 z = make_uint4(0u, 0u, 0u, 0u);
        #pragma unroll
        for (int j = 0; j < 64; j += 8)
            *(uint4*)(Hs + (size_t)er * PADK + cbase + j) = z;
    }
    __syncthreads();

    const int warp = tid >> 5, lane = tid & 31;
    float acc[16][4];
    #pragma unroll
    for (int n = 0; n < 16; n++)
        acc[n][0] = acc[n][1] = acc[n][2] = acc[n][3] = 0.f;

    warp_mma_16x128(Hs + (size_t)warp * 16 * PADK, Ws, acc, lane);

    const int g = lane >> 2, t = lane & 3;
    const int r0 = e0 + warp * 16 + g;
    #pragma unroll
    for (int n = 0; n < 16; n++) {
        int col = n * 8 + 2 * t;
        float bx = __ldg(b2 + col), by = __ldg(b2 + col + 1);
        if (r0 < n_edges) {
            float2 v = make_float2(acc[n][0] + bx, acc[n][1] + by);
            *(float2*)(out + (size_t)r0 * 128 + col) = v;
        }
        if (r0 + 8 < n_edges) {
            float2 v = make_float2(acc[n][2] + bx, acc[n][3] + by);
            *(float2*)(out + (size_t)(r0 + 8) * 128 + col) = v;
        }
    }
}

// ---------------------------------------------------------------------------
extern "C" void kernel_launch(void* const* d_in, const int* in_sizes, int n_in,
                              void* d_out, int out_size)
{
    const float* x   = (const float*)d_in[0];
    const void*  ei  = d_in[1];
    const float* W1  = (const float*)d_in[2];
    const float* b1  = (const float*)d_in[3];
    const float* W2  = (const float*)d_in[4];
    const float* b2  = (const float*)d_in[5];
    float* out = (float*)d_out;

    const int n_nodes = in_sizes[0] / 128;
    const int n_edges = in_sizes[1] / 2;

    const int smem_bytes = 2 * 128 * PADK * (int)sizeof(__half);  // 69632
    static bool attr_set = false;
    if (!attr_set) {
        cudaFuncSetAttribute(node_gemm_kernel,
                             cudaFuncAttributeMaxDynamicSharedMemorySize, smem_bytes);
        cudaFuncSetAttribute(edge_kernel,
                             cudaFuncAttributeMaxDynamicSharedMemorySize, smem_bytes);
        attr_set = true;
    }

    detect_idx_kernel<<<1, 256>>>((const unsigned int*)ei);

    dim3 g1((n_nodes + 127) / 128, 2);
    node_gemm_kernel<<<g1, 256, smem_bytes>>>(x, W1, n_nodes);

    int g2 = (n_edges + 127) / 128;
    edge_kernel<<<g2, 256, smem_bytes>>>(ei, b1, W2, b2, out, n_edges);
}

// round 2
// speedup vs baseline: 1.3720x; 1.3720x over previous
#include <cuda_runtime.h>
#include <cuda_fp16.h>
#include <cstdint>

#define PADK 136           // halfs per smem row (128 + 8 pad) -> conflict-free LDSM
#define MAXNODES 50000

// Scratch: per-node transformed features, fp16.
// Y[n, 0:128]  = x[n] @ W1a   (src half),  Y[n,128:256] = x[n] @ W1b (dst half)
__device__ __half g_Y[(size_t)MAXNODES * 256];
__device__ int g_idx64;

// ---------------------------------------------------------------------------
__device__ __forceinline__ unsigned sptr(const void* p) {
    return (unsigned)__cvta_generic_to_shared(p);
}

__device__ __forceinline__ void ldsm4(unsigned a, unsigned& r0, unsigned& r1,
                                      unsigned& r2, unsigned& r3) {
    asm volatile("ldmatrix.sync.aligned.m8n8.x4.shared.b16 {%0,%1,%2,%3}, [%4];\n"
                 : "=r"(r0), "=r"(r1), "=r"(r2), "=r"(r3) : "r"(a));
}

__device__ __forceinline__ void mma16816(float* c, unsigned a0, unsigned a1,
                                         unsigned a2, unsigned a3,
                                         unsigned b0, unsigned b1) {
    asm volatile(
        "mma.sync.aligned.m16n8k16.row.col.f32.f16.f16.f32 "
        "{%0,%1,%2,%3}, {%4,%5,%6,%7}, {%8,%9}, {%0,%1,%2,%3};\n"
        : "+f"(c[0]), "+f"(c[1]), "+f"(c[2]), "+f"(c[3])
        : "r"(a0), "r"(a1), "r"(a2), "r"(a3), "r"(b0), "r"(b1));
}

// Warp-level 16x128x128 GEMM, all fragments via ldmatrix.x4.
// Aw: warp's 16-row strip in smem (row stride PADK halfs).
// Bs: [128][PADK], Bs[n][k] = B[k][n] (n-major).
__device__ __forceinline__ void warp_mma_ldsm(const __half* Aw, const __half* Bs,
                                              float acc[16][4], int lane) {
    // A groups: rows (lane&15), col +8 for upper half of lanes
    unsigned a_base = sptr(Aw + (size_t)(lane & 15) * PADK + ((lane & 16) ? 8 : 0));
    // B groups: n = (lane&7) + ((lane&16)?8:0), k offset = (lane&8)?8:0
    const int bn = (lane & 7) + ((lane & 16) ? 8 : 0);
    const int bk = (lane & 8) ? 8 : 0;
    unsigned b_base = sptr(Bs + (size_t)bn * PADK + bk);

    #pragma unroll
    for (int k0 = 0; k0 < 128; k0 += 16) {
        unsigned a0, a1, a2, a3;
        ldsm4(a_base + k0 * 2, a0, a1, a2, a3);
        #pragma unroll
        for (int np = 0; np < 8; np++) {   // pair of n-tiles per iteration
            unsigned b0, b1, b2, b3;
            ldsm4(b_base + (unsigned)(np * 16 * PADK * 2) + k0 * 2, b0, b1, b2, b3);
            mma16816(acc[2 * np],     a0, a1, a2, a3, b0, b1);
            mma16816(acc[2 * np + 1], a0, a1, a2, a3, b2, b3);
        }
    }
}

// ---------------------------------------------------------------------------
// Kernel 1: Y[:, half*128 : +128] = x @ W1[half*128 : +128, :]  (+ idx detect)
// grid (ceil(N/128), 2), block 256.
// ---------------------------------------------------------------------------
__global__ __launch_bounds__(256, 2)
void node_gemm_kernel(const float* __restrict__ x,
                      const float* __restrict__ W1,
                      const void* __restrict__ ei,
                      int n_nodes) {
    extern __shared__ __half smem[];
    __half* As = smem;                 // [128][PADK]
    __half* Bs = smem + 128 * PADK;    // Bs[n][k] = W1[k+off][n]

    const int row0 = blockIdx.x * 128;
    const int half_sel = blockIdx.y;
    const int tid = threadIdx.x;

    // Fold edge_index dtype detection into the first block (one warp).
    // int64 little-endian with values < 2^31 => all odd 32-bit words are 0.
    if (blockIdx.x == 0 && half_sel == 0 && tid < 32) {
        const unsigned* w = (const unsigned*)ei;
        unsigned v = w[2 * tid + 1] | w[2 * (tid + 32) + 1];
        int any_nz = __any_sync(0xffffffffu, v != 0u);
        if (tid == 0) g_idx64 = any_nz ? 0 : 1;
    }

    // x tile fp32 -> fp16 (vectorized, zero-pad OOB rows)
    for (int i = tid; i < 128 * 32; i += 256) {
        int r = i >> 5, c4 = i & 31;
        int gr = row0 + r;
        float4 v = make_float4(0.f, 0.f, 0.f, 0.f);
        if (gr < n_nodes) v = ((const float4*)x)[(size_t)gr * 32 + c4];
        __half* dst = As + (size_t)r * PADK + c4 * 4;
        dst[0] = __float2half(v.x); dst[1] = __float2half(v.y);
        dst[2] = __float2half(v.z); dst[3] = __float2half(v.w);
    }
    // W1 slab transposed: Bs[n][k] = W1[(k + 128*half)*128 + n]
    for (int i = tid; i < 128 * 128; i += 256) {
        int k = i >> 7, n = i & 127;   // consecutive tid -> consecutive n (coalesced)
        Bs[(size_t)n * PADK + k] =
            __float2half(W1[(size_t)(k + 128 * half_sel) * 128 + n]);
    }
    __syncthreads();

    const int warp = tid >> 5, lane = tid & 31;
    float acc[16][4];
    #pragma unroll
    for (int n = 0; n < 16; n++)
        acc[n][0] = acc[n][1] = acc[n][2] = acc[n][3] = 0.f;

    warp_mma_ldsm(As + (size_t)warp * 16 * PADK, Bs, acc, lane);

    const int g = lane >> 2, t = lane & 3;
    const int r0 = row0 + warp * 16 + g;
    __half* Yb = g_Y + (size_t)half_sel * 128;
    #pragma unroll
    for (int n = 0; n < 16; n++) {
        int col = n * 8 + 2 * t;
        if (r0 < n_nodes)
            *(__half2*)(Yb + (size_t)r0 * 256 + col) =
                __floats2half2_rn(acc[n][0], acc[n][1]);
        if (r0 + 8 < n_nodes)
            *(__half2*)(Yb + (size_t)(r0 + 8) * 256 + col) =
                __floats2half2_rn(acc[n][2], acc[n][3]);
    }
}

// ---------------------------------------------------------------------------
// Kernel 2 (persistent): per tile of 128 edges:
//   h = relu(Y[src,:128] + Y[dst,128:] + b1);  out = h @ W2 + b2
// grid 296 (2 CTAs/SM), block 256. W2 staged to smem ONCE per CTA.
// ---------------------------------------------------------------------------
__global__ __launch_bounds__(256, 2)
void edge_kernel(const void* __restrict__ edge_index,
                 const float* __restrict__ b1,
                 const float* __restrict__ W2,
                 const float* __restrict__ b2,
                 float* __restrict__ out,
                 int n_edges) {
    extern __shared__ __half smem[];
    __half* Hs = smem;                 // [128][PADK]  h tile
    __half* Ws = smem + 128 * PADK;    // Ws[n][k] = W2[k][n]

    const int tid = threadIdx.x;
    const int warp = tid >> 5, lane = tid & 31;
    const int g = lane >> 2, t = lane & 3;

    // One-time W2 stage (transposed; global side coalesced)
    for (int i = tid; i < 128 * 128; i += 256) {
        int k = i >> 7, n = i & 127;
        Ws[(size_t)n * PADK + k] = __float2half(W2[i]);  // W2[k*128+n] == W2[i]
    }

    // Preload this thread's b2 values (epilogue cols n*8 + 2t)
    float2 breg[16];
    #pragma unroll
    for (int n = 0; n < 16; n++)
        breg[n] = *(const float2*)(b2 + n * 8 + 2 * t);

    const int is64 = g_idx64;
    const long long* idx64 = (const long long*)edge_index;
    const int*       idx32 = (const int*)edge_index;

    const int er = tid >> 1;              // edge-in-tile this thread gathers
    const int cbase = (tid & 1) * 64;     // 64-col half handled
    const int n_tiles = (n_edges + 127) >> 7;

    for (int tile = blockIdx.x; tile < n_tiles; tile += gridDim.x) {
        const int e0 = tile << 7;
        const int e = e0 + er;

        // ---- gather + bias + relu -> Hs ----
        if (e < n_edges) {
            long long s, d;
            if (is64) { s = idx64[e]; d = idx64[(size_t)n_edges + e]; }
            else      { s = idx32[e]; d = idx32[(size_t)n_edges + e]; }
            const __half* Ya = g_Y + (size_t)s * 256;          // src half
            const __half* Yd = g_Y + (size_t)d * 256 + 128;    // dst half
            #pragma unroll
            for (int j = 0; j < 64; j += 8) {
                int c = cbase + j;
                uint4 va = *(const uint4*)(Ya + c);
                uint4 vb = *(const uint4*)(Yd + c);
                const __half2* ha = (const __half2*)&va;
                const __half2* hb = (const __half2*)&vb;
                __half2 r[4];
                #pragma unroll
                for (int q = 0; q < 4; q++) {
                    float2 fa = __half22float2(ha[q]);
                    float2 fb = __half22float2(hb[q]);
                    float2 bb = __ldg((const float2*)(b1 + c + 2 * q));
                    float vx = fmaxf(fa.x + fb.x + bb.x, 0.f);
                    float vy = fmaxf(fa.y + fb.y + bb.y, 0.f);
                    r[q] = __floats2half2_rn(vx, vy);
                }
                *(uint4*)(Hs + (size_t)er * PADK + c) = *(const uint4*)r;
            }
        } else {
            uint4 z = make_uint4(0u, 0u, 0u, 0u);
            #pragma unroll
            for (int j = 0; j < 64; j += 8)
                *(uint4*)(Hs + (size_t)er * PADK + cbase + j) = z;
        }
        __syncthreads();

        // ---- 128x128x128 GEMM ----
        float acc[16][4];
        #pragma unroll
        for (int n = 0; n < 16; n++)
            acc[n][0] = acc[n][1] = acc[n][2] = acc[n][3] = 0.f;

        warp_mma_ldsm(Hs + (size_t)warp * 16 * PADK, Ws, acc, lane);

        // ---- epilogue: +b2, store fp32 ----
        const int r0 = e0 + warp * 16 + g;
        #pragma unroll
        for (int n = 0; n < 16; n++) {
            int col = n * 8 + 2 * t;
            if (r0 < n_edges) {
                float2 v = make_float2(acc[n][0] + breg[n].x, acc[n][1] + breg[n].y);
                *(float2*)(out + (size_t)r0 * 128 + col) = v;
            }
            if (r0 + 8 < n_edges) {
                float2 v = make_float2(acc[n][2] + breg[n].x, acc[n][3] + breg[n].y);
                *(float2*)(out + (size_t)(r0 + 8) * 128 + col) = v;
            }
        }
        __syncthreads();   // Hs reuse guard
    }
}

// ---------------------------------------------------------------------------
extern "C" void kernel_launch(void* const* d_in, const int* in_sizes, int n_in,
                              void* d_out, int out_size) {
    const float* x  = (const float*)d_in[0];
    const void*  ei = d_in[1];
    const float* W1 = (const float*)d_in[2];
    const float* b1 = (const float*)d_in[3];
    const float* W2 = (const float*)d_in[4];
    const float* b2 = (const float*)d_in[5];
    float* out = (float*)d_out;

    const int n_nodes = in_sizes[0] / 128;
    const int n_edges = in_sizes[1] / 2;

    const int smem_bytes = 2 * 128 * PADK * (int)sizeof(__half);  // 69632
    static bool attr_set = false;
    if (!attr_set) {
        cudaFuncSetAttribute(node_gemm_kernel,
                             cudaFuncAttributeMaxDynamicSharedMemorySize, smem_bytes);
        cudaFuncSetAttribute(edge_kernel,
                             cudaFuncAttributeMaxDynamicSharedMemorySize, smem_bytes);
        attr_set = true;
    }

    dim3 g1((n_nodes + 127) / 128, 2);
    node_gemm_kernel<<<g1, 256, smem_bytes>>>(x, W1, ei, n_nodes);

    int n_tiles = (n_edges + 127) / 128;
    int g2 = n_tiles < 296 ? n_tiles : 296;
    edge_kernel<<<g2, 256, smem_bytes>>>(ei, b1, W2, b2, out, n_edges);
}

// round 4
// speedup vs baseline: 2.1628x; 1.5763x over previous
#include <cuda_runtime.h>
#include <cuda_fp16.h>
#include <cstdint>

#define PADK 136           // halfs per smem row (128 + 8 pad) -> conflict-free LDSM
#define FULLMASK 0xffffffffu

// Scratch: per-node transformed features, fp16.
// Y[n, 0:128] = x[n] @ W1a (src half),  Y[n,128:256] = x[n] @ W1b (dst half)
__device__ __half g_Y[(size_t)50000 * 256];
__device__ int g_idx64;

// ---------------------------------------------------------------------------
__device__ __forceinline__ unsigned sptr(const void* p) {
    return (unsigned)__cvta_generic_to_shared(p);
}
__device__ __forceinline__ void ldsm4(unsigned a, unsigned& r0, unsigned& r1,
                                      unsigned& r2, unsigned& r3) {
    asm volatile("ldmatrix.sync.aligned.m8n8.x4.shared.b16 {%0,%1,%2,%3}, [%4];\n"
                 : "=r"(r0), "=r"(r1), "=r"(r2), "=r"(r3) : "r"(a));
}
__device__ __forceinline__ void mma16816(float* c, unsigned a0, unsigned a1,
                                         unsigned a2, unsigned a3,
                                         unsigned b0, unsigned b1) {
    asm volatile(
        "mma.sync.aligned.m16n8k16.row.col.f32.f16.f16.f32 "
        "{%0,%1,%2,%3}, {%4,%5,%6,%7}, {%8,%9}, {%0,%1,%2,%3};\n"
        : "+f"(c[0]), "+f"(c[1]), "+f"(c[2]), "+f"(c[3])
        : "r"(a0), "r"(a1), "r"(a2), "r"(a3), "r"(b0), "r"(b1));
}

// ---------------------------------------------------------------------------
// Warp-level 32x64x128 GEMM (2 m16 strips x 8 n8 groups), ldmatrix.x4 only.
// Aw: warp's 32-row strip (row stride PADK); Bw: warp's 64 n-rows (n-major).
// ---------------------------------------------------------------------------
__device__ __forceinline__ void warp_mma_32x64(const __half* Aw, const __half* Bw,
                                               float acc[2][8][4], int lane) {
    unsigned a_addr = sptr(Aw + (size_t)(lane & 15) * PADK + ((lane & 16) ? 8 : 0));
    unsigned b_addr = sptr(Bw + (size_t)((lane & 7) + ((lane & 16) ? 8 : 0)) * PADK
                              + ((lane & 8) ? 8 : 0));
    #pragma unroll
    for (int k0 = 0; k0 < 128; k0 += 16) {
        unsigned a0[4], a1[4];
        ldsm4(a_addr + k0 * 2, a0[0], a0[1], a0[2], a0[3]);
        ldsm4(a_addr + 16 * PADK * 2 + k0 * 2, a1[0], a1[1], a1[2], a1[3]);
        #pragma unroll
        for (int np = 0; np < 4; np++) {
            unsigned b0, b1, b2, b3;
            ldsm4(b_addr + (unsigned)(np * 16 * PADK * 2) + k0 * 2, b0, b1, b2, b3);
            mma16816(acc[0][2 * np],     a0[0], a0[1], a0[2], a0[3], b0, b1);
            mma16816(acc[0][2 * np + 1], a0[0], a0[1], a0[2], a0[3], b2, b3);
            mma16816(acc[1][2 * np],     a1[0], a1[1], a1[2], a1[3], b0, b1);
            mma16816(acc[1][2 * np + 1], a1[0], a1[1], a1[2], a1[3], b2, b3);
        }
    }
}

// ---------------------------------------------------------------------------
// Node kernel (persistent, block 512, 1 CTA/SM):
//   Y[tile, :] = x[tile] @ [W1a | W1b]   (256 output cols per row)
// W1 staged once per CTA; A double-buffered; warps: 4M x 4N (32x64 tiles).
// ---------------------------------------------------------------------------
__global__ __launch_bounds__(512, 1)
void node_gemm_kernel(const float* __restrict__ x,
                      const float* __restrict__ W1,
                      const void* __restrict__ ei,
                      int n_nodes) {
    extern __shared__ __half smem[];
    __half* As0 = smem;                   // [128][PADK]
    __half* As1 = smem + 128 * PADK;
    __half* Ws  = smem + 2 * 128 * PADK;  // [256 out-cols][PADK k]

    const int tid = threadIdx.x;

    // edge_index dtype detection (int64 LE small values => odd words all 0)
    if (blockIdx.x == 0 && tid < 32) {
        const unsigned* w = (const unsigned*)ei;
        unsigned v = w[2 * tid + 1] | w[2 * (tid + 32) + 1];
        int any_nz = __any_sync(FULLMASK, v != 0u);
        if (tid == 0) g_idx64 = any_nz ? 0 : 1;
    }

    // Stage W1 once: Ws[c][k] = W1[(k + 128*(c>>7))*128 + (c&127)], coalesced in c.
    for (int i = tid; i < 256 * 128; i += 512) {
        int c = i & 255, k = i >> 8;
        Ws[(size_t)c * PADK + k] =
            __float2half(W1[(size_t)(k + ((c >> 7) << 7)) * 128 + (c & 127)]);
    }

    const int warp = tid >> 5, lane = tid & 31;
    const int wm = warp & 3, wn = warp >> 2;      // 4M x 4N
    const int g = lane >> 2, t = lane & 3;
    const int n_tiles = (n_nodes + 127) >> 7;

    int li = 0;
    for (int tile = blockIdx.x; tile < n_tiles; tile += gridDim.x, li++) {
        __half* As = (li & 1) ? As1 : As0;
        const int row0 = tile << 7;

        // Load x tile fp32 -> fp16 (coalesced float4, zero-pad OOB rows)
        for (int i = tid; i < 128 * 32; i += 512) {
            int r = i >> 5, c4 = i & 31;
            int gr = row0 + r;
            float4 v = make_float4(0.f, 0.f, 0.f, 0.f);
            if (gr < n_nodes) v = ((const float4*)x)[(size_t)gr * 32 + c4];
            __half* dst = As + (size_t)r * PADK + c4 * 4;
            dst[0] = __float2half(v.x); dst[1] = __float2half(v.y);
            dst[2] = __float2half(v.z); dst[3] = __float2half(v.w);
        }
        __syncthreads();

        float acc[2][8][4];
        #pragma unroll
        for (int mi = 0; mi < 2; mi++)
            #pragma unroll
            for (int n8 = 0; n8 < 8; n8++)
                acc[mi][n8][0] = acc[mi][n8][1] = acc[mi][n8][2] = acc[mi][n8][3] = 0.f;

        warp_mma_32x64(As + (size_t)(wm * 32) * PADK,
                       Ws + (size_t)(wn * 64) * PADK, acc, lane);

        // Epilogue: write Y halfs (col c = wn*64 + n8*8 + 2t; Y row stride 256)
        #pragma unroll
        for (int mi = 0; mi < 2; mi++) {
            const int r0 = row0 + wm * 32 + mi * 16 + g;
            #pragma unroll
            for (int n8 = 0; n8 < 8; n8++) {
                int col = wn * 64 + n8 * 8 + 2 * t;
                if (r0 < n_nodes)
                    *(__half2*)(g_Y + (size_t)r0 * 256 + col) =
                        __floats2half2_rn(acc[mi][n8][0], acc[mi][n8][1]);
                if (r0 + 8 < n_nodes)
                    *(__half2*)(g_Y + (size_t)(r0 + 8) * 256 + col) =
                        __floats2half2_rn(acc[mi][n8][2], acc[mi][n8][3]);
            }
        }
        // no second sync: next iteration writes the other A buffer
    }
}

// ---------------------------------------------------------------------------
// Edge kernel (persistent, block 256, 2 CTAs/SM):
//   h = relu(Y[src,:128] + Y[dst,128:] + b1);  out = h @ W2 + b2
// Warp-cooperative gather (whole warp loads one node-half contiguously),
// H double-buffered, 32x64 warp tiles (4M x 2N), single sync per tile.
// ---------------------------------------------------------------------------
__global__ __launch_bounds__(256, 2)
void edge_kernel(const void* __restrict__ edge_index,
                 const float* __restrict__ b1,
                 const float* __restrict__ W2,
                 const float* __restrict__ b2,
                 float* __restrict__ out,
                 int n_edges) {
    extern __shared__ __half smem[];
    __half* Hs0 = smem;                   // [128][PADK]
    __half* Hs1 = smem + 128 * PADK;
    __half* Ws  = smem + 2 * 128 * PADK;  // [128 n][PADK k] = W2[k][n]

    const int tid = threadIdx.x;
    const int warp = tid >> 5, lane = tid & 31;
    const int wm = warp & 3, wn = warp >> 2;      // 4M x 2N
    const int g = lane >> 2, t = lane & 3;

    // Stage W2 once (transposed; coalesced on global side)
    for (int i = tid; i < 128 * 128; i += 256) {
        int k = i >> 7, n = i & 127;
        Ws[(size_t)n * PADK + k] = __float2half(W2[i]);  // W2[k*128+n] == W2[i]
    }

    // Per-lane constants: b1 slice (cols lane*4..+3) and b2 for epilogue cols
    const float4 b1v = *(const float4*)(b1 + lane * 4);
    float2 breg[8];
    #pragma unroll
    for (int n8 = 0; n8 < 8; n8++)
        breg[n8] = *(const float2*)(b2 + wn * 64 + n8 * 8 + 2 * t);

    const int is64 = g_idx64;
    const long long* idx64 = (const long long*)edge_index;
    const int*       idx32 = (const int*)edge_index;
    const int n_tiles = (n_edges + 127) >> 7;

    int li = 0;
    for (int tile = blockIdx.x; tile < n_tiles; tile += gridDim.x, li++) {
        __half* Hs = (li & 1) ? Hs1 : Hs0;
        const int e0 = tile << 7;

        // ---- warp-cooperative gather: warp handles 16 edges ----
        // lanes 0-15 hold src idx of edge i=lane; lanes 16-31 dst idx of i=lane-16
        {
            int myE = e0 + (warp << 4) + (lane & 15);
            if (myE >= n_edges) myE = n_edges - 1;
            size_t off = (lane < 16) ? (size_t)myE : (size_t)n_edges + (size_t)myE;
            int vidx = is64 ? (int)idx64[off] : idx32[off];

            __half* Hrow = Hs + (size_t)(warp << 4) * PADK + lane * 4;
            #pragma unroll
            for (int i = 0; i < 16; i++) {
                int s = __shfl_sync(FULLMASK, vidx, i);
                int d = __shfl_sync(FULLMASK, vidx, 16 + i);
                // whole warp reads 256B contiguous from each node-half
                uint2 va = *(const uint2*)(g_Y + (size_t)s * 256 + lane * 4);
                uint2 vd = *(const uint2*)(g_Y + (size_t)d * 256 + 128 + lane * 4);
                float2 fa0 = __half22float2(*(const __half2*)&va.x);
                float2 fd0 = __half22float2(*(const __half2*)&vd.x);
                float2 fa1 = __half22float2(*(const __half2*)&va.y);
                float2 fd1 = __half22float2(*(const __half2*)&vd.y);
                __half2 r0 = __floats2half2_rn(fmaxf(fa0.x + fd0.x + b1v.x, 0.f),
                                               fmaxf(fa0.y + fd0.y + b1v.y, 0.f));
                __half2 r1 = __floats2half2_rn(fmaxf(fa1.x + fd1.x + b1v.z, 0.f),
                                               fmaxf(fa1.y + fd1.y + b1v.w, 0.f));
                uint2 rv;
                rv.x = *(const unsigned*)&r0;
                rv.y = *(const unsigned*)&r1;
                *(uint2*)(Hrow + (size_t)i * PADK) = rv;
            }
        }
        __syncthreads();

        // ---- 32x64 warp-tile GEMM ----
        float acc[2][8][4];
        #pragma unroll
        for (int mi = 0; mi < 2; mi++)
            #pragma unroll
            for (int n8 = 0; n8 < 8; n8++)
                acc[mi][n8][0] = acc[mi][n8][1] = acc[mi][n8][2] = acc[mi][n8][3] = 0.f;

        warp_mma_32x64(Hs + (size_t)(wm * 32) * PADK,
                       Ws + (size_t)(wn * 64) * PADK, acc, lane);

        // ---- epilogue: +b2, store fp32 ----
        #pragma unroll
        for (int mi = 0; mi < 2; mi++) {
            const int r0 = e0 + wm * 32 + mi * 16 + g;
            #pragma unroll
            for (int n8 = 0; n8 < 8; n8++) {
                int col = wn * 64 + n8 * 8 + 2 * t;
                if (r0 < n_edges) {
                    float2 v = make_float2(acc[mi][n8][0] + breg[n8].x,
                                           acc[mi][n8][1] + breg[n8].y);
                    *(float2*)(out + (size_t)r0 * 128 + col) = v;
                }
                if (r0 + 8 < n_edges) {
                    float2 v = make_float2(acc[mi][n8][2] + breg[n8].x,
                                           acc[mi][n8][3] + breg[n8].y);
                    *(float2*)(out + (size_t)(r0 + 8) * 128 + col) = v;
                }
            }
        }
        // no second sync: next iteration gathers into the other H buffer
    }
}

// ---------------------------------------------------------------------------
extern "C" void kernel_launch(void* const* d_in, const int* in_sizes, int n_in,
                              void* d_out, int out_size) {
    const float* x  = (const float*)d_in[0];
    const void*  ei = d_in[1];
    const float* W1 = (const float*)d_in[2];
    const float* b1 = (const float*)d_in[3];
    const float* W2 = (const float*)d_in[4];
    const float* b2 = (const float*)d_in[5];
    float* out = (float*)d_out;

    const int n_nodes = in_sizes[0] / 128;
    const int n_edges = in_sizes[1] / 2;

    const int node_smem = (2 * 128 + 256) * PADK * (int)sizeof(__half);  // 139264
    const int edge_smem = 3 * 128 * PADK * (int)sizeof(__half);          // 104448
    static bool attr_set = false;
    if (!attr_set) {
        cudaFuncSetAttribute(node_gemm_kernel,
                             cudaFuncAttributeMaxDynamicSharedMemorySize, node_smem);
        cudaFuncSetAttribute(edge_kernel,
                             cudaFuncAttributeMaxDynamicSharedMemorySize, edge_smem);
        attr_set = true;
    }

    const int node_tiles = (n_nodes + 127) / 128;
    int g1 = node_tiles < 148 ? node_tiles : 148;
    node_gemm_kernel<<<g1, 512, node_smem>>>(x, W1, ei, n_nodes);

    const int edge_tiles = (n_edges + 127) / 128;
    int g2 = edge_tiles < 296 ? edge_tiles : 296;
    edge_kernel<<<g2, 256, edge_smem>>>(ei, b1, W2, b2, out, n_edges);
}